// round 15
// baseline (speedup 1.0000x reference)
#include <cuda_runtime.h>
#include <math.h>

// ---------------------------------------------------------------------------
// ReducedNet: QuantConv3d(1->1, k=(5,3,5), s=(2,1,2)) + bias -> MaxPool3d(2)
//             -> flatten(343) -> QuantFC(343->128)+ReLU -> QuantFC(128->4)
//             -> softmax
// Inputs (metadata order): x, w_conv, b_conv, w_fc1, b_fc1, w_fc2, b_fc2
// Output: float32 [2048, 4]
// ---------------------------------------------------------------------------

#define BATCH   2048
#define XD      31
#define XH      16
#define XW      31
#define XVOL    (XD*XH*XW)        // 15376 floats per batch element
#define NF      343               // pooled/flattened feature count (7*7*7)
#define NFP     344               // padded for float4 access

// persistent scratch (no allocations allowed)
__device__ float g_qconv[75];            // quantized conv weights
__device__ float g_qfc1t[NFP * 128];     // quantized fc1 weights, TRANSPOSED [k][c], k padded
__device__ float g_qfc2[512];            // quantized fc2 weights [4][128]
__device__ float g_f[(size_t)BATCH * NFP]; // pooled features, padded rows

// ---------------------------------------------------------------------------
// Kernel 1: fake-quant the three weight tensors (per-tensor symmetric 4-bit).
// q = clip(round(w/s), -8, 7) * s,  s = max|w| / 7.  rintf == round-half-even.
// blockIdx.x: 0 = w_conv(75), 1 = w_fc1(128x343, write transposed), 2 = w_fc2(512)
// ---------------------------------------------------------------------------
__global__ void quant_kernel(const float* __restrict__ w_conv,
                             const float* __restrict__ w_fc1,
                             const float* __restrict__ w_fc2) {
    __shared__ float red[256];
    const int tid = threadIdx.x;

    const float* src;
    int n;
    if (blockIdx.x == 0)      { src = w_conv; n = 75; }
    else if (blockIdx.x == 1) { src = w_fc1;  n = 343 * 128; }
    else                      { src = w_fc2;  n = 512; }

    float m = 0.f;
    for (int i = tid; i < n; i += 256) m = fmaxf(m, fabsf(src[i]));
    red[tid] = m;
    __syncthreads();
    #pragma unroll
    for (int off = 128; off > 0; off >>= 1) {
        if (tid < off) red[tid] = fmaxf(red[tid], red[tid + off]);
        __syncthreads();
    }
    const float s = red[0] * (1.0f / 7.0f);
    const float inv_s = 1.0f / s;

    if (blockIdx.x == 0) {
        for (int i = tid; i < 75; i += 256) {
            float q = fminf(fmaxf(rintf(w_conv[i] * inv_s), -8.f), 7.f) * s;
            g_qconv[i] = q;
        }
    } else if (blockIdx.x == 1) {
        // write transposed: g_qfc1t[k*128 + c] = q(w_fc1[c*343 + k])
        for (int i = tid; i < 343 * 128; i += 256) {
            int k = i >> 7, c = i & 127;
            float q = fminf(fmaxf(rintf(w_fc1[c * 343 + k] * inv_s), -8.f), 7.f) * s;
            g_qfc1t[i] = q;
        }
        if (tid < 128) g_qfc1t[343 * 128 + tid] = 0.f;  // zero pad row (k=343)
    } else {
        for (int i = tid; i < 512; i += 256) {
            float q = fminf(fmaxf(rintf(w_fc2[i] * inv_s), -8.f), 7.f) * s;
            g_qfc2[i] = q;
        }
    }
}

// ---------------------------------------------------------------------------
// Kernel 2: fused conv3d + bias + maxpool, one block per batch element.
// x slice staged in dynamic smem. Each pooled output (pd,ph,pw) maxes a 2x2x2
// window of conv outputs; the 8 conv results share a 7x4x7 input region, which
// we walk row-by-row (28 rows x 7 loads = 196 LDS for 600 FMA).
// Conv weights live in registers (75), bias added after the max.
// ---------------------------------------------------------------------------
__global__ void __launch_bounds__(256, 2) conv_pool_kernel(
    const float* __restrict__ x, const float* __restrict__ b_conv) {
    extern __shared__ float xs[];   // 15376 floats
    const int b = blockIdx.x, tid = threadIdx.x;

    // stage x[b] into smem (float4: 15376/4 = 3844)
    const float4* src = (const float4*)(x + (size_t)b * XVOL);
    float4* dst = (float4*)xs;
    #pragma unroll 4
    for (int i = tid; i < XVOL / 4; i += 256) dst[i] = src[i];

    // conv weights -> registers (uniform across block, L1/L2 broadcast)
    float wr[75];
    #pragma unroll
    for (int i = 0; i < 75; ++i) wr[i] = g_qconv[i];
    const float bias = b_conv[0];
    __syncthreads();

    float* fout = g_f + (size_t)b * NFP;

    #pragma unroll 1
    for (int p = tid; p < NF; p += 256) {
        const int pw = p % 7;
        const int t  = p / 7;
        const int ph = t % 7;
        const int pd = t / 7;

        // acc[dd*4 + hh*2 + ww] = conv(od=2pd+dd, oh=2ph+hh, ow=2pw+ww)
        float acc[8];
        #pragma unroll
        for (int i = 0; i < 8; ++i) acc[i] = 0.f;

        const float* basep = xs + ((4 * pd) * XH + (2 * ph)) * XW + 4 * pw;

        #pragma unroll
        for (int d = 0; d < 7; ++d) {        // input depth offset (D = 4pd + d)
            #pragma unroll
            for (int h = 0; h < 4; ++h) {    // input height offset (H = 2ph + h)
                const float* row = basep + d * (XH * XW) + h * XW;
                float x7[7];
                #pragma unroll
                for (int i = 0; i < 7; ++i) x7[i] = row[i];

                #pragma unroll
                for (int dd = 0; dd < 2; ++dd) {
                    const int kd = d - 2 * dd;       // compile-time after unroll
                    if (kd < 0 || kd > 4) continue;
                    #pragma unroll
                    for (int hh = 0; hh < 2; ++hh) {
                        const int kh = h - hh;
                        if (kh < 0 || kh > 2) continue;
                        const int wb = (kd * 3 + kh) * 5;
                        #pragma unroll
                        for (int kw = 0; kw < 5; ++kw) {
                            const float wv = wr[wb + kw];
                            acc[dd * 4 + hh * 2 + 0] = fmaf(wv, x7[kw],     acc[dd * 4 + hh * 2 + 0]);
                            acc[dd * 4 + hh * 2 + 1] = fmaf(wv, x7[kw + 2], acc[dd * 4 + hh * 2 + 1]);
                        }
                    }
                }
            }
        }
        float mv = acc[0];
        #pragma unroll
        for (int i = 1; i < 8; ++i) mv = fmaxf(mv, acc[i]);
        fout[p] = mv + bias;
    }
    if (tid == 0) fout[NF] = 0.f;   // zero the pad column
}

// ---------------------------------------------------------------------------
// Kernel 3: FC1 (343->128) + ReLU + FC2 (128->4) + softmax.
// 16 batch rows per block. f tile in smem (broadcast LDS.128 reads),
// fc1 weights streamed coalesced from L2 (transposed layout).
// ---------------------------------------------------------------------------
__global__ void __launch_bounds__(256) fc_kernel(
    const float* __restrict__ b_fc1, const float* __restrict__ b_fc2,
    float* __restrict__ out) {
    __shared__ float fs[16][NFP];    // 22016 B
    __shared__ float a1s[16][132];   // stride 132 -> conflict-free column reads
    __shared__ float s2s[16][4];

    const int tid  = threadIdx.x;
    const int row0 = blockIdx.x * 16;

    // load 16 padded feature rows (16*344/4 = 1376 float4)
    const float4* src = (const float4*)(g_f + (size_t)row0 * NFP);
    float4* dst = (float4*)&fs[0][0];
    for (int i = tid; i < 16 * NFP / 4; i += 256) dst[i] = src[i];
    __syncthreads();

    const int c  = tid & 127;    // fc1 output column
    const int rg = tid >> 7;     // row group: rows rg*8 .. rg*8+7

    float acc[8];
    #pragma unroll
    for (int i = 0; i < 8; ++i) acc[i] = 0.f;

    const float* wt = g_qfc1t + c;
    for (int k = 0; k < NFP; k += 4) {
        const float w0 = wt[(k + 0) * 128];
        const float w1 = wt[(k + 1) * 128];
        const float w2 = wt[(k + 2) * 128];
        const float w3 = wt[(k + 3) * 128];
        #pragma unroll
        for (int r = 0; r < 8; ++r) {
            const float4 f4 = *(const float4*)&fs[rg * 8 + r][k];
            acc[r] = fmaf(f4.x, w0, acc[r]);
            acc[r] = fmaf(f4.y, w1, acc[r]);
            acc[r] = fmaf(f4.z, w2, acc[r]);
            acc[r] = fmaf(f4.w, w3, acc[r]);
        }
    }

    const float b1 = b_fc1[c];
    #pragma unroll
    for (int r = 0; r < 8; ++r)
        a1s[rg * 8 + r][c] = fmaxf(acc[r] + b1, 0.f);
    __syncthreads();

    // FC2: 64 threads, (row, out) = (tid>>2, tid&3)
    if (tid < 64) {
        const int rr = tid >> 2, o = tid & 3;
        float s = b_fc2[o];
        const float* w2p = g_qfc2 + o * 128;
        #pragma unroll 4
        for (int k = 0; k < 128; ++k) s = fmaf(a1s[rr][k], w2p[k], s);
        s2s[rr][o] = s;
    }
    __syncthreads();

    // softmax over 4, one thread per row
    if (tid < 16) {
        const float v0 = s2s[tid][0], v1 = s2s[tid][1];
        const float v2 = s2s[tid][2], v3 = s2s[tid][3];
        const float m  = fmaxf(fmaxf(v0, v1), fmaxf(v2, v3));
        const float e0 = expf(v0 - m), e1 = expf(v1 - m);
        const float e2 = expf(v2 - m), e3 = expf(v3 - m);
        const float inv = 1.f / (e0 + e1 + e2 + e3);
        *(float4*)(out + (size_t)(row0 + tid) * 4) =
            make_float4(e0 * inv, e1 * inv, e2 * inv, e3 * inv);
    }
}

// ---------------------------------------------------------------------------
extern "C" void kernel_launch(void* const* d_in, const int* in_sizes, int n_in,
                              void* d_out, int out_size) {
    const float* x      = (const float*)d_in[0];
    const float* w_conv = (const float*)d_in[1];
    const float* b_conv = (const float*)d_in[2];
    const float* w_fc1  = (const float*)d_in[3];
    const float* b_fc1  = (const float*)d_in[4];
    const float* w_fc2  = (const float*)d_in[5];
    const float* b_fc2  = (const float*)d_in[6];
    float* out = (float*)d_out;

    // idempotent, immediate (not a stream op) — needed for 60 KB dynamic smem
    cudaFuncSetAttribute(conv_pool_kernel,
                         cudaFuncAttributeMaxDynamicSharedMemorySize, XVOL * 4);

    quant_kernel<<<3, 256>>>(w_conv, w_fc1, w_fc2);
    conv_pool_kernel<<<BATCH, 256, XVOL * 4>>>(x, b_conv);
    fc_kernel<<<BATCH / 16, 256>>>(b_fc1, b_fc2, out);
}

// round 16
// speedup vs baseline: 1.0020x; 1.0020x over previous
#include <cuda_runtime.h>
#include <math.h>

// ---------------------------------------------------------------------------
// ReducedNet: QuantConv3d(1->1, k=(5,3,5), s=(2,1,2)) + bias -> MaxPool3d(2)
//             -> flatten(343) -> QuantFC(343->128)+ReLU -> QuantFC(128->4)
//             -> softmax
// Inputs (metadata order): x, w_conv, b_conv, w_fc1, b_fc1, w_fc2, b_fc2
// Output: float32 [2048, 4]
// ---------------------------------------------------------------------------

#define BATCH   2048
#define XD      31
#define XH      16
#define XW      31
#define XVOL    (XD*XH*XW)        // 15376 floats per batch element
#define NF      343               // pooled/flattened feature count (7*7*7)
#define NFP     344               // padded for float4 access

// persistent scratch (no allocations allowed)
__device__ float g_qconv[75];            // quantized conv weights
__device__ float g_qfc1t[NFP * 128];     // quantized fc1 weights, TRANSPOSED [k][c], k padded
__device__ float g_qfc2[512];            // quantized fc2 weights [4][128]
__device__ float g_f[(size_t)BATCH * NFP]; // pooled features, padded rows

// ---------------------------------------------------------------------------
// Kernel 1: fake-quant the three weight tensors (per-tensor symmetric 4-bit).
// q = clip(round(w/s), -8, 7) * s,  s = max|w| / 7.  rintf == round-half-even.
// blockIdx.x: 0 = w_conv(75), 1 = w_fc1(128x343, write transposed), 2 = w_fc2(512)
// ---------------------------------------------------------------------------
__global__ void quant_kernel(const float* __restrict__ w_conv,
                             const float* __restrict__ w_fc1,
                             const float* __restrict__ w_fc2) {
    __shared__ float red[256];
    const int tid = threadIdx.x;

    const float* src;
    int n;
    if (blockIdx.x == 0)      { src = w_conv; n = 75; }
    else if (blockIdx.x == 1) { src = w_fc1;  n = 343 * 128; }
    else                      { src = w_fc2;  n = 512; }

    float m = 0.f;
    for (int i = tid; i < n; i += 256) m = fmaxf(m, fabsf(src[i]));
    red[tid] = m;
    __syncthreads();
    #pragma unroll
    for (int off = 128; off > 0; off >>= 1) {
        if (tid < off) red[tid] = fmaxf(red[tid], red[tid + off]);
        __syncthreads();
    }
    const float s = red[0] * (1.0f / 7.0f);
    const float inv_s = 1.0f / s;

    if (blockIdx.x == 0) {
        for (int i = tid; i < 75; i += 256) {
            float q = fminf(fmaxf(rintf(w_conv[i] * inv_s), -8.f), 7.f) * s;
            g_qconv[i] = q;
        }
    } else if (blockIdx.x == 1) {
        // write transposed: g_qfc1t[k*128 + c] = q(w_fc1[c*343 + k])
        for (int i = tid; i < 343 * 128; i += 256) {
            int k = i >> 7, c = i & 127;
            float q = fminf(fmaxf(rintf(w_fc1[c * 343 + k] * inv_s), -8.f), 7.f) * s;
            g_qfc1t[i] = q;
        }
        if (tid < 128) g_qfc1t[343 * 128 + tid] = 0.f;  // zero pad row (k=343)
    } else {
        for (int i = tid; i < 512; i += 256) {
            float q = fminf(fmaxf(rintf(w_fc2[i] * inv_s), -8.f), 7.f) * s;
            g_qfc2[i] = q;
        }
    }
}

// ---------------------------------------------------------------------------
// Kernel 2: fused conv3d + bias + maxpool, one block per batch element.
// x slice staged in dynamic smem. Each pooled output (pd,ph,pw) maxes a 2x2x2
// window of conv outputs; the 8 conv results share a 7x4x7 input region, which
// we walk row-by-row (28 rows x 7 loads = 196 LDS for 600 FMA).
// Conv weights live in registers (75), bias added after the max.
// ---------------------------------------------------------------------------
__global__ void __launch_bounds__(256, 2) conv_pool_kernel(
    const float* __restrict__ x, const float* __restrict__ b_conv) {
    extern __shared__ float xs[];   // 15376 floats
    const int b = blockIdx.x, tid = threadIdx.x;

    // stage x[b] into smem (float4: 15376/4 = 3844)
    const float4* src = (const float4*)(x + (size_t)b * XVOL);
    float4* dst = (float4*)xs;
    #pragma unroll 4
    for (int i = tid; i < XVOL / 4; i += 256) dst[i] = src[i];

    // conv weights -> registers (uniform across block, L1/L2 broadcast)
    float wr[75];
    #pragma unroll
    for (int i = 0; i < 75; ++i) wr[i] = g_qconv[i];
    const float bias = b_conv[0];
    __syncthreads();

    float* fout = g_f + (size_t)b * NFP;

    #pragma unroll 1
    for (int p = tid; p < NF; p += 256) {
        const int pw = p % 7;
        const int t  = p / 7;
        const int ph = t % 7;
        const int pd = t / 7;

        // acc[dd*4 + hh*2 + ww] = conv(od=2pd+dd, oh=2ph+hh, ow=2pw+ww)
        float acc[8];
        #pragma unroll
        for (int i = 0; i < 8; ++i) acc[i] = 0.f;

        const float* basep = xs + ((4 * pd) * XH + (2 * ph)) * XW + 4 * pw;

        #pragma unroll
        for (int d = 0; d < 7; ++d) {        // input depth offset (D = 4pd + d)
            #pragma unroll
            for (int h = 0; h < 4; ++h) {    // input height offset (H = 2ph + h)
                const float* row = basep + d * (XH * XW) + h * XW;
                float x7[7];
                #pragma unroll
                for (int i = 0; i < 7; ++i) x7[i] = row[i];

                #pragma unroll
                for (int dd = 0; dd < 2; ++dd) {
                    const int kd = d - 2 * dd;       // compile-time after unroll
                    if (kd < 0 || kd > 4) continue;
                    #pragma unroll
                    for (int hh = 0; hh < 2; ++hh) {
                        const int kh = h - hh;
                        if (kh < 0 || kh > 2) continue;
                        const int wb = (kd * 3 + kh) * 5;
                        #pragma unroll
                        for (int kw = 0; kw < 5; ++kw) {
                            const float wv = wr[wb + kw];
                            acc[dd * 4 + hh * 2 + 0] = fmaf(wv, x7[kw],     acc[dd * 4 + hh * 2 + 0]);
                            acc[dd * 4 + hh * 2 + 1] = fmaf(wv, x7[kw + 2], acc[dd * 4 + hh * 2 + 1]);
                        }
                    }
                }
            }
        }
        float mv = acc[0];
        #pragma unroll
        for (int i = 1; i < 8; ++i) mv = fmaxf(mv, acc[i]);
        fout[p] = mv + bias;
    }
    if (tid == 0) fout[NF] = 0.f;   // zero the pad column
}

// ---------------------------------------------------------------------------
// Kernel 3: FC1 (343->128) + ReLU + FC2 (128->4) + softmax.
// 16 batch rows per block. f tile in smem (broadcast LDS.128 reads),
// fc1 weights streamed coalesced from L2 (transposed layout).
// ---------------------------------------------------------------------------
__global__ void __launch_bounds__(256) fc_kernel(
    const float* __restrict__ b_fc1, const float* __restrict__ b_fc2,
    float* __restrict__ out) {
    __shared__ float fs[16][NFP];    // 22016 B
    __shared__ float a1s[16][132];   // stride 132 -> conflict-free column reads
    __shared__ float s2s[16][4];

    const int tid  = threadIdx.x;
    const int row0 = blockIdx.x * 16;

    // load 16 padded feature rows (16*344/4 = 1376 float4)
    const float4* src = (const float4*)(g_f + (size_t)row0 * NFP);
    float4* dst = (float4*)&fs[0][0];
    for (int i = tid; i < 16 * NFP / 4; i += 256) dst[i] = src[i];
    __syncthreads();

    const int c  = tid & 127;    // fc1 output column
    const int rg = tid >> 7;     // row group: rows rg*8 .. rg*8+7

    float acc[8];
    #pragma unroll
    for (int i = 0; i < 8; ++i) acc[i] = 0.f;

    const float* wt = g_qfc1t + c;
    for (int k = 0; k < NFP; k += 4) {
        const float w0 = wt[(k + 0) * 128];
        const float w1 = wt[(k + 1) * 128];
        const float w2 = wt[(k + 2) * 128];
        const float w3 = wt[(k + 3) * 128];
        #pragma unroll
        for (int r = 0; r < 8; ++r) {
            const float4 f4 = *(const float4*)&fs[rg * 8 + r][k];
            acc[r] = fmaf(f4.x, w0, acc[r]);
            acc[r] = fmaf(f4.y, w1, acc[r]);
            acc[r] = fmaf(f4.z, w2, acc[r]);
            acc[r] = fmaf(f4.w, w3, acc[r]);
        }
    }

    const float b1 = b_fc1[c];
    #pragma unroll
    for (int r = 0; r < 8; ++r)
        a1s[rg * 8 + r][c] = fmaxf(acc[r] + b1, 0.f);
    __syncthreads();

    // FC2: 64 threads, (row, out) = (tid>>2, tid&3)
    if (tid < 64) {
        const int rr = tid >> 2, o = tid & 3;
        float s = b_fc2[o];
        const float* w2p = g_qfc2 + o * 128;
        #pragma unroll 4
        for (int k = 0; k < 128; ++k) s = fmaf(a1s[rr][k], w2p[k], s);
        s2s[rr][o] = s;
    }
    __syncthreads();

    // softmax over 4, one thread per row
    if (tid < 16) {
        const float v0 = s2s[tid][0], v1 = s2s[tid][1];
        const float v2 = s2s[tid][2], v3 = s2s[tid][3];
        const float m  = fmaxf(fmaxf(v0, v1), fmaxf(v2, v3));
        const float e0 = expf(v0 - m), e1 = expf(v1 - m);
        const float e2 = expf(v2 - m), e3 = expf(v3 - m);
        const float inv = 1.f / (e0 + e1 + e2 + e3);
        *(float4*)(out + (size_t)(row0 + tid) * 4) =
            make_float4(e0 * inv, e1 * inv, e2 * inv, e3 * inv);
    }
}

// ---------------------------------------------------------------------------
extern "C" void kernel_launch(void* const* d_in, const int* in_sizes, int n_in,
                              void* d_out, int out_size) {
    const float* x      = (const float*)d_in[0];
    const float* w_conv = (const float*)d_in[1];
    const float* b_conv = (const float*)d_in[2];
    const float* w_fc1  = (const float*)d_in[3];
    const float* b_fc1  = (const float*)d_in[4];
    const float* w_fc2  = (const float*)d_in[5];
    const float* b_fc2  = (const float*)d_in[6];
    float* out = (float*)d_out;

    // idempotent, immediate (not a stream op) — needed for 60 KB dynamic smem
    cudaFuncSetAttribute(conv_pool_kernel,
                         cudaFuncAttributeMaxDynamicSharedMemorySize, XVOL * 4);

    quant_kernel<<<3, 256>>>(w_conv, w_fc1, w_fc2);
    conv_pool_kernel<<<BATCH, 256, XVOL * 4>>>(x, b_conv);
    fc_kernel<<<BATCH / 16, 256>>>(b_fc1, b_fc2, out);
}

// round 17
// speedup vs baseline: 1.0022x; 1.0002x over previous
#include <cuda_runtime.h>
#include <math.h>

// ---------------------------------------------------------------------------
// ReducedNet: QuantConv3d(1->1, k=(5,3,5), s=(2,1,2)) + bias -> MaxPool3d(2)
//             -> flatten(343) -> QuantFC(343->128)+ReLU -> QuantFC(128->4)
//             -> softmax
// Inputs (metadata order): x, w_conv, b_conv, w_fc1, b_fc1, w_fc2, b_fc2
// Output: float32 [2048, 4]
// ---------------------------------------------------------------------------

#define BATCH   2048
#define XD      31
#define XH      16
#define XW      31
#define XVOL    (XD*XH*XW)        // 15376 floats per batch element
#define NF      343               // pooled/flattened feature count (7*7*7)
#define NFP     344               // padded for float4 access

// persistent scratch (no allocations allowed)
__device__ float g_qconv[75];            // quantized conv weights
__device__ float g_qfc1t[NFP * 128];     // quantized fc1 weights, TRANSPOSED [k][c], k padded
__device__ float g_qfc2[512];            // quantized fc2 weights [4][128]
__device__ float g_f[(size_t)BATCH * NFP]; // pooled features, padded rows

// ---------------------------------------------------------------------------
// Kernel 1: fake-quant the three weight tensors (per-tensor symmetric 4-bit).
// q = clip(round(w/s), -8, 7) * s,  s = max|w| / 7.  rintf == round-half-even.
// blockIdx.x: 0 = w_conv(75), 1 = w_fc1(128x343, write transposed), 2 = w_fc2(512)
// ---------------------------------------------------------------------------
__global__ void quant_kernel(const float* __restrict__ w_conv,
                             const float* __restrict__ w_fc1,
                             const float* __restrict__ w_fc2) {
    __shared__ float red[256];
    const int tid = threadIdx.x;

    const float* src;
    int n;
    if (blockIdx.x == 0)      { src = w_conv; n = 75; }
    else if (blockIdx.x == 1) { src = w_fc1;  n = 343 * 128; }
    else                      { src = w_fc2;  n = 512; }

    float m = 0.f;
    for (int i = tid; i < n; i += 256) m = fmaxf(m, fabsf(src[i]));
    red[tid] = m;
    __syncthreads();
    #pragma unroll
    for (int off = 128; off > 0; off >>= 1) {
        if (tid < off) red[tid] = fmaxf(red[tid], red[tid + off]);
        __syncthreads();
    }
    const float s = red[0] * (1.0f / 7.0f);
    const float inv_s = 1.0f / s;

    if (blockIdx.x == 0) {
        for (int i = tid; i < 75; i += 256) {
            float q = fminf(fmaxf(rintf(w_conv[i] * inv_s), -8.f), 7.f) * s;
            g_qconv[i] = q;
        }
    } else if (blockIdx.x == 1) {
        // write transposed: g_qfc1t[k*128 + c] = q(w_fc1[c*343 + k])
        for (int i = tid; i < 343 * 128; i += 256) {
            int k = i >> 7, c = i & 127;
            float q = fminf(fmaxf(rintf(w_fc1[c * 343 + k] * inv_s), -8.f), 7.f) * s;
            g_qfc1t[i] = q;
        }
        if (tid < 128) g_qfc1t[343 * 128 + tid] = 0.f;  // zero pad row (k=343)
    } else {
        for (int i = tid; i < 512; i += 256) {
            float q = fminf(fmaxf(rintf(w_fc2[i] * inv_s), -8.f), 7.f) * s;
            g_qfc2[i] = q;
        }
    }
}

// ---------------------------------------------------------------------------
// Kernel 2: fused conv3d + bias + maxpool, one block per batch element.
// x slice staged in dynamic smem. Each pooled output (pd,ph,pw) maxes a 2x2x2
// window of conv outputs; the 8 conv results share a 7x4x7 input region, which
// we walk row-by-row (28 rows x 7 loads = 196 LDS for 600 FMA).
// Conv weights live in registers (75), bias added after the max.
// ---------------------------------------------------------------------------
__global__ void __launch_bounds__(256, 2) conv_pool_kernel(
    const float* __restrict__ x, const float* __restrict__ b_conv) {
    extern __shared__ float xs[];   // 15376 floats
    const int b = blockIdx.x, tid = threadIdx.x;

    // stage x[b] into smem (float4: 15376/4 = 3844)
    const float4* src = (const float4*)(x + (size_t)b * XVOL);
    float4* dst = (float4*)xs;
    #pragma unroll 4
    for (int i = tid; i < XVOL / 4; i += 256) dst[i] = src[i];

    // conv weights -> registers (uniform across block, L1/L2 broadcast)
    float wr[75];
    #pragma unroll
    for (int i = 0; i < 75; ++i) wr[i] = g_qconv[i];
    const float bias = b_conv[0];
    __syncthreads();

    float* fout = g_f + (size_t)b * NFP;

    #pragma unroll 1
    for (int p = tid; p < NF; p += 256) {
        const int pw = p % 7;
        const int t  = p / 7;
        const int ph = t % 7;
        const int pd = t / 7;

        // acc[dd*4 + hh*2 + ww] = conv(od=2pd+dd, oh=2ph+hh, ow=2pw+ww)
        float acc[8];
        #pragma unroll
        for (int i = 0; i < 8; ++i) acc[i] = 0.f;

        const float* basep = xs + ((4 * pd) * XH + (2 * ph)) * XW + 4 * pw;

        #pragma unroll
        for (int d = 0; d < 7; ++d) {        // input depth offset (D = 4pd + d)
            #pragma unroll
            for (int h = 0; h < 4; ++h) {    // input height offset (H = 2ph + h)
                const float* row = basep + d * (XH * XW) + h * XW;
                float x7[7];
                #pragma unroll
                for (int i = 0; i < 7; ++i) x7[i] = row[i];

                #pragma unroll
                for (int dd = 0; dd < 2; ++dd) {
                    const int kd = d - 2 * dd;       // compile-time after unroll
                    if (kd < 0 || kd > 4) continue;
                    #pragma unroll
                    for (int hh = 0; hh < 2; ++hh) {
                        const int kh = h - hh;
                        if (kh < 0 || kh > 2) continue;
                        const int wb = (kd * 3 + kh) * 5;
                        #pragma unroll
                        for (int kw = 0; kw < 5; ++kw) {
                            const float wv = wr[wb + kw];
                            acc[dd * 4 + hh * 2 + 0] = fmaf(wv, x7[kw],     acc[dd * 4 + hh * 2 + 0]);
                            acc[dd * 4 + hh * 2 + 1] = fmaf(wv, x7[kw + 2], acc[dd * 4 + hh * 2 + 1]);
                        }
                    }
                }
            }
        }
        float mv = acc[0];
        #pragma unroll
        for (int i = 1; i < 8; ++i) mv = fmaxf(mv, acc[i]);
        fout[p] = mv + bias;
    }
    if (tid == 0) fout[NF] = 0.f;   // zero the pad column
}

// ---------------------------------------------------------------------------
// Kernel 3: FC1 (343->128) + ReLU + FC2 (128->4) + softmax.
// 16 batch rows per block. f tile in smem (broadcast LDS.128 reads),
// fc1 weights streamed coalesced from L2 (transposed layout).
// ---------------------------------------------------------------------------
__global__ void __launch_bounds__(256) fc_kernel(
    const float* __restrict__ b_fc1, const float* __restrict__ b_fc2,
    float* __restrict__ out) {
    __shared__ float fs[16][NFP];    // 22016 B
    __shared__ float a1s[16][132];   // stride 132 -> conflict-free column reads
    __shared__ float s2s[16][4];

    const int tid  = threadIdx.x;
    const int row0 = blockIdx.x * 16;

    // load 16 padded feature rows (16*344/4 = 1376 float4)
    const float4* src = (const float4*)(g_f + (size_t)row0 * NFP);
    float4* dst = (float4*)&fs[0][0];
    for (int i = tid; i < 16 * NFP / 4; i += 256) dst[i] = src[i];
    __syncthreads();

    const int c  = tid & 127;    // fc1 output column
    const int rg = tid >> 7;     // row group: rows rg*8 .. rg*8+7

    float acc[8];
    #pragma unroll
    for (int i = 0; i < 8; ++i) acc[i] = 0.f;

    const float* wt = g_qfc1t + c;
    for (int k = 0; k < NFP; k += 4) {
        const float w0 = wt[(k + 0) * 128];
        const float w1 = wt[(k + 1) * 128];
        const float w2 = wt[(k + 2) * 128];
        const float w3 = wt[(k + 3) * 128];
        #pragma unroll
        for (int r = 0; r < 8; ++r) {
            const float4 f4 = *(const float4*)&fs[rg * 8 + r][k];
            acc[r] = fmaf(f4.x, w0, acc[r]);
            acc[r] = fmaf(f4.y, w1, acc[r]);
            acc[r] = fmaf(f4.z, w2, acc[r]);
            acc[r] = fmaf(f4.w, w3, acc[r]);
        }
    }

    const float b1 = b_fc1[c];
    #pragma unroll
    for (int r = 0; r < 8; ++r)
        a1s[rg * 8 + r][c] = fmaxf(acc[r] + b1, 0.f);
    __syncthreads();

    // FC2: 64 threads, (row, out) = (tid>>2, tid&3)
    if (tid < 64) {
        const int rr = tid >> 2, o = tid & 3;
        float s = b_fc2[o];
        const float* w2p = g_qfc2 + o * 128;
        #pragma unroll 4
        for (int k = 0; k < 128; ++k) s = fmaf(a1s[rr][k], w2p[k], s);
        s2s[rr][o] = s;
    }
    __syncthreads();

    // softmax over 4, one thread per row
    if (tid < 16) {
        const float v0 = s2s[tid][0], v1 = s2s[tid][1];
        const float v2 = s2s[tid][2], v3 = s2s[tid][3];
        const float m  = fmaxf(fmaxf(v0, v1), fmaxf(v2, v3));
        const float e0 = expf(v0 - m), e1 = expf(v1 - m);
        const float e2 = expf(v2 - m), e3 = expf(v3 - m);
        const float inv = 1.f / (e0 + e1 + e2 + e3);
        *(float4*)(out + (size_t)(row0 + tid) * 4) =
            make_float4(e0 * inv, e1 * inv, e2 * inv, e3 * inv);
    }
}

// ---------------------------------------------------------------------------
extern "C" void kernel_launch(void* const* d_in, const int* in_sizes, int n_in,
                              void* d_out, int out_size) {
    const float* x      = (const float*)d_in[0];
    const float* w_conv = (const float*)d_in[1];
    const float* b_conv = (const float*)d_in[2];
    const float* w_fc1  = (const float*)d_in[3];
    const float* b_fc1  = (const float*)d_in[4];
    const float* w_fc2  = (const float*)d_in[5];
    const float* b_fc2  = (const float*)d_in[6];
    float* out = (float*)d_out;

    // idempotent, immediate (not a stream op) — needed for 60 KB dynamic smem
    cudaFuncSetAttribute(conv_pool_kernel,
                         cudaFuncAttributeMaxDynamicSharedMemorySize, XVOL * 4);

    quant_kernel<<<3, 256>>>(w_conv, w_fc1, w_fc2);
    conv_pool_kernel<<<BATCH, 256, XVOL * 4>>>(x, b_conv);
    fc_kernel<<<BATCH / 16, 256>>>(b_fc1, b_fc2, out);
}